// round 9
// baseline (speedup 1.0000x reference)
#include <cuda_runtime.h>

// y (4,1,512,512) fp32; BINS=256, VMIN=0, VMAX=1, SIGMA=30.
// One persistent kernel, 148 CTAs (single wave):
//  Phase 1: hybrid histogram — per thread ~7 pixels: 3 via shared-memory
//           atomics (smem atomic ALU), ~4 via REDG into per-CTA-private
//           global partials (L2 atomic path) -> the two units run in parallel.
//           Shared hist exported via plain STG to g_shm[cta].
//  [bar0]   Distributed coalesced merge: 128 CTAs x 64 bins sum 37 part + 37 shm
//           -> float g_n[b][m].
//  [bar1]   Each CTA zeros its own g_part (replay-safe). 128 row-CTAs correlate
//           g_n with sigmoid-difference table K (8 output bins each), entropy
//           terms accumulated in 2^-50 fixed point (exact, order-independent);
//           last-done CTA writes 1/d and resets accumulators.

#define NB 4
#define HW 262144
#define FINE 2048
#define GRID 148
#define CPB 37
#define F4B 65536                  // float4 per batch
#define TBL 4096                   // K table alloc (4088 valid)
#define TOFF 2040
#define KSTEP (30.0f/2048.0f)
#define NTHR 1024
#define FXSCALE 1125899906842624.0          /* 2^50  */
#define FXINV   8.881784197001252e-16       /* 2^-50 */

__device__ unsigned int       g_part[GRID][FINE]; // REDG targets; self-zeroed each call
__device__ unsigned int       g_shm[GRID][FINE];  // STG export of shared hist (overwritten)
__device__ float              g_n[NB][FINE];      // merged counts (overwritten)
__device__ float              g_K[TBL];
__device__ unsigned long long g_dacc;
__device__ unsigned int       g_done;
__device__ unsigned int       g_bar[2];

__device__ __forceinline__ float sneg(float t) {       // sigmoid, t <= 0
    float e = expf(t);
    return e / (1.0f + e);
}
__device__ __forceinline__ float sigdiff(float a1, float a2) { // a1 > a2
    if (a2 >= 0.0f) return sneg(-a2) - sneg(-a1);
    if (a1 <= 0.0f) return sneg(a1) - sneg(a2);
    return (1.0f - sneg(-a1)) - sneg(a2);
}

// Self-resetting two-phase counting grid barrier (re-entrant across replays).
__device__ __forceinline__ void gridbar(int k) {
    __syncthreads();
    if (threadIdx.x == 0) {
        __threadfence();
        atomicAdd(&g_bar[k], 1u);
        while (*((volatile unsigned int*)&g_bar[k]) < (unsigned)GRID) { }
        unsigned int old = atomicAdd(&g_bar[k], 1u);
        if (old == 2u * GRID - 1u) atomicExch(&g_bar[k], 0u);
        __threadfence();
    }
    __syncthreads();
}

__device__ __forceinline__ int binof(float v) {
    return min((int)(v * 2048.0f), 2047);
}

__global__ void __launch_bounds__(NTHR, 1) k_fused(const float* __restrict__ y,
                                                   float* __restrict__ out) {
    __shared__ unsigned int shh[FINE];       // phase1 hist; phase2 reused as float n
    __shared__ float s_mrg[16][64];
    __shared__ float s_part[8][4];
    __shared__ float s_term[8];
    __shared__ int   s_last;

    const int tid = threadIdx.x;
    const int cta = blockIdx.x;

    // ---- K table: 28 entries per CTA (148*28 >= 4096) ----
    if (tid < 28) {
        int idx = cta * 28 + tid;
        if (idx < TBL) {
            float v = 0.0f;
            if (idx < TOFF + FINE) {
                float q = (float)(idx - TOFF);
                v = sigdiff(KSTEP * (q + 0.5f), KSTEP * (q - 7.5f));
            }
            g_K[idx] = v;
        }
    }

    // ---- Phase 1: hybrid shared-ATOMS + private-REDG histogram ----
    shh[tid] = 0u;
    shh[tid + 1024] = 0u;
    __syncthreads();

    {
        int b     = cta / CPB;                 // batch 0..3 (37 CTAs each)
        int local = cta - b * CPB;
        // split 65536 float4 over 37 CTAs: 9 CTAs get 1772, 28 get 1771
        int base  = b * F4B + local * 1771 + min(local, 9);
        int len   = 1771 + (local < 9 ? 1 : 0);

        const float4* yp = (const float4*)y;
        unsigned int* gp = g_part[cta];

        float4 v0 = yp[base + tid];
        bool   has2 = (tid + 1024) < len;
        float4 v1;
        if (has2) v1 = yp[base + 1024 + tid];

        // 3 pixels -> smem atomic ALU
        atomicAdd(&shh[binof(v0.x)], 1u);
        atomicAdd(&shh[binof(v0.y)], 1u);
        atomicAdd(&shh[binof(v0.z)], 1u);
        // remaining pixels -> L2 RED path (per-CTA-private addresses)
        atomicAdd(&gp[binof(v0.w)], 1u);
        if (has2) {
            atomicAdd(&gp[binof(v1.x)], 1u);
            atomicAdd(&gp[binof(v1.y)], 1u);
            atomicAdd(&gp[binof(v1.z)], 1u);
            atomicAdd(&gp[binof(v1.w)], 1u);
        }
    }
    __syncthreads();

    // export shared hist with plain coalesced stores (no atomics)
    g_shm[cta][tid]        = shh[tid];
    g_shm[cta][tid + 1024] = shh[tid + 1024];

    gridbar(0);

    // ---- Merge: CTA k<128 handles batch k>>5, bins [(k&31)*64, +64) ----
    if (cta < 128) {
        int b2 = cta >> 5;
        int m0 = (cta & 31) * 64;
        int c  = tid >> 6;                     // source group 0..15
        int ml = tid & 63;
        unsigned int s = 0;
        #pragma unroll
        for (int cc = 0; cc < 3; cc++) {
            int src = c + cc * 16;
            if (src < CPB)
                s += g_part[b2 * CPB + src][m0 + ml]
                   + g_shm [b2 * CPB + src][m0 + ml];
        }
        s_mrg[c][ml] = (float)s;               // exact: < 2^24
        __syncthreads();
        if (tid < 64) {
            float t = 0.0f;
            #pragma unroll
            for (int i = 0; i < 16; i++) t += s_mrg[i][tid];
            g_n[b2][m0 + tid] = t;
        }
    }

    gridbar(1);

    // zero own REDG partial for the next replay (merge consumers are done)
    ((uint2*)g_part[cta])[tid] = make_uint2(0u, 0u);

    // ---- Phase 2: 128 row-CTAs (8 output bins each); rest exit ----
    if (cta >= 128) return;

    const int bb = cta >> 5;
    const int g  = cta & 31;
    float* snf = (float*)shh;
    if (tid < FINE / 4)
        ((float4*)snf)[tid] = ((const float4*)g_n[bb])[tid];
    __syncthreads();

    {
        int w = tid >> 5, lane = tid & 31;
        int r = w >> 2, q = w & 3;
        int i = g * 8 + r;                     // output bin 0..255
        const float*  np = snf + q * 512;
        const float4* Kp = (const float4*)(g_K + (TOFF - 8 * i) + q * 512);

        float4 acc = make_float4(0.f, 0.f, 0.f, 0.f);
        #pragma unroll
        for (int it = 0; it < 4; it++) {       // 4 * 128 = 512 taps per warp
            int m = it * 128 + lane * 4;
            float4 nv = *(const float4*)(np + m);
            float4 kv = __ldg(Kp + (m >> 2));
            acc.x += nv.x * kv.x; acc.y += nv.y * kv.y;
            acc.z += nv.z * kv.z; acc.w += nv.w * kv.w;
        }
        float a = (acc.x + acc.y) + (acc.z + acc.w);
        #pragma unroll
        for (int off = 16; off; off >>= 1)
            a += __shfl_down_sync(0xffffffffu, a, off);
        if (lane == 0) s_part[r][q] = a;
    }
    __syncthreads();

    if (tid < 8) {
        float h  = (s_part[tid][0] + s_part[tid][1]) + (s_part[tid][2] + s_part[tid][3]);
        float pr = h * (1.0f / (float)HW) + 1e-6f;
        s_term[tid] = -pr * logf(pr);
    }
    __syncthreads();

    if (tid == 0) {
        float s = ((s_term[0] + s_term[1]) + (s_term[2] + s_term[3]))
                + ((s_term[4] + s_term[5]) + (s_term[6] + s_term[7]));
        unsigned long long qv = (unsigned long long)((double)s * FXSCALE + 0.5);
        atomicAdd(&g_dacc, qv);
        __threadfence();
        unsigned int old = atomicAdd(&g_done, 1u);
        s_last = (old == 127u);
    }
    __syncthreads();

    if (s_last && tid == 0) {
        unsigned long long tot = atomicExch(&g_dacc, 0ULL);
        atomicExch(&g_done, 0u);
        out[0] = (float)(1.0 / ((double)tot * FXINV));
    }
}

extern "C" void kernel_launch(void* const* d_in, const int* in_sizes, int n_in,
                              void* d_out, int out_size) {
    (void)in_sizes; (void)n_in; (void)out_size;
    k_fused<<<GRID, NTHR>>>((const float*)d_in[0], (float*)d_out);
}

// round 11
// speedup vs baseline: 1.3145x; 1.3145x over previous
#include <cuda_runtime.h>
#include <cstdint>

// y (4,1,512,512) fp32; BINS=256, VMIN=0, VMAX=1, SIGMA=30.
// One persistent kernel, 148 CTAs (single wave):
//  Phase 1: per-CTA SHARED 2048-bin fine histogram (smem atomics = measured
//           fastest counting path), then ONE cp.reduce.async.bulk per CTA
//           merges it into global integer bins (TMA engine does the L2-side
//           add; no per-lane RED issue cost).
//  [grid barrier]
//  Phase 2: 128 CTAs correlate counts with sigmoid-difference table K
//           (8 output bins each); per-CTA entropy partial accumulated in
//           2^-50 fixed point (exact, order-independent); last-done CTA
//           writes 1/d and re-zeros state for graph replay.

#define NB 4
#define HW 262144
#define FINE 2048
#define GRID 148
#define CPB 37                     // histogram CTAs per batch
#define F4B 65536                  // float4 per batch
#define TBL 4096                   // K table alloc (4088 valid)
#define TOFF 2040                  // K index offset: q = idx - TOFF
#define KSTEP (30.0f/2048.0f)
#define NTHR 1024
#define FXSCALE 1125899906842624.0          /* 2^50  */
#define FXINV   8.881784197001252e-16       /* 2^-50 */

__device__ unsigned int       g_nu[NB][FINE];  // zero at load; re-zeroed each call
__device__ float              g_K[TBL];
__device__ unsigned long long g_dacc;
__device__ unsigned int       g_done;
__device__ unsigned int       g_bar;

__device__ __forceinline__ float sneg(float t) {       // sigmoid, t <= 0
    float e = expf(t);
    return e / (1.0f + e);
}
__device__ __forceinline__ float sigdiff(float a1, float a2) { // a1 > a2
    if (a2 >= 0.0f) return sneg(-a2) - sneg(-a1);
    if (a1 <= 0.0f) return sneg(a1) - sneg(a2);
    return (1.0f - sneg(-a1)) - sneg(a2);
}

// Self-resetting two-phase counting grid barrier (re-entrant across replays).
__device__ __forceinline__ void gridbar() {
    __syncthreads();
    if (threadIdx.x == 0) {
        __threadfence();
        atomicAdd(&g_bar, 1u);
        while (*((volatile unsigned int*)&g_bar) < (unsigned)GRID) { }
        unsigned int old = atomicAdd(&g_bar, 1u);
        if (old == 2u * GRID - 1u) atomicExch(&g_bar, 0u);
        __threadfence();
    }
    __syncthreads();
}

__device__ __forceinline__ int binof(float v) {
    return min((int)(v * 2048.0f), 2047);
}

__global__ void __launch_bounds__(NTHR, 1) k_fused(const float* __restrict__ y,
                                                   float* __restrict__ out) {
    __shared__ unsigned int shh[FINE];       // phase1 hist; phase2 reused as float n
    __shared__ float s_part[8][4];
    __shared__ float s_term[8];
    __shared__ int   s_last;

    const int tid = threadIdx.x;
    const int cta = blockIdx.x;

    // ---- K table: 28 entries per CTA (148*28 >= 4096); overlaps phase 1 ----
    if (tid < 28) {
        int idx = cta * 28 + tid;
        if (idx < TBL) {
            float v = 0.0f;
            if (idx < TOFF + FINE) {           // 4088 valid
                float q = (float)(idx - TOFF);
                v = sigdiff(KSTEP * (q + 0.5f), KSTEP * (q - 7.5f));
            }
            g_K[idx] = v;
        }
    }

    // ---- Phase 1: per-CTA shared fine histogram ----
    shh[tid] = 0u;
    shh[tid + 1024] = 0u;
    __syncthreads();

    int b = cta / CPB;                         // batch 0..3 (37 CTAs each)
    {
        int local = cta - b * CPB;
        // split 65536 float4 over 37 CTAs: 9 CTAs get 1772, 28 get 1771
        int base  = b * F4B + local * 1771 + min(local, 9);
        int len   = 1771 + (local < 9 ? 1 : 0);

        const float4* yp = (const float4*)y;

        float4 v0 = yp[base + tid];
        bool   has2 = (tid + 1024) < len;
        float4 v1;
        if (has2) v1 = yp[base + 1024 + tid];

        atomicAdd(&shh[binof(v0.x)], 1u);
        atomicAdd(&shh[binof(v0.y)], 1u);
        atomicAdd(&shh[binof(v0.z)], 1u);
        atomicAdd(&shh[binof(v0.w)], 1u);
        if (has2) {
            atomicAdd(&shh[binof(v1.x)], 1u);
            atomicAdd(&shh[binof(v1.y)], 1u);
            atomicAdd(&shh[binof(v1.z)], 1u);
            atomicAdd(&shh[binof(v1.w)], 1u);
        }
    }
    __syncthreads();

    // ---- Merge: single TMA bulk add-reduction SMEM -> g_nu[b] ----
    if (tid == 0) {
        asm volatile("fence.proxy.async.shared::cta;" ::: "memory");
        uint32_t src = (uint32_t)__cvta_generic_to_shared(shh);
        asm volatile(
            "cp.reduce.async.bulk.global.shared::cta.bulk_group.add.u32 [%0], [%1], %2;"
            :: "l"(g_nu[b]), "r"(src), "r"((int)(FINE * 4)) : "memory");
        asm volatile("cp.async.bulk.commit_group;" ::: "memory");
        asm volatile("cp.async.bulk.wait_group 0;" ::: "memory");
    }

    gridbar();

    // ---- Phase 2: 128 row-CTAs (8 output bins each); rest exit ----
    if (cta >= 128) return;

    const int bb = cta >> 5;                   // batch
    const int g  = cta & 31;                   // bin group within batch
    float* snf = (float*)shh;
    if (tid < FINE / 4) {
        uint4 u = ((const uint4*)g_nu[bb])[tid];
        ((float4*)snf)[tid] = make_float4((float)u.x, (float)u.y,
                                          (float)u.z, (float)u.w);
    }
    __syncthreads();

    {
        int w = tid >> 5, lane = tid & 31;
        int r = w >> 2, q = w & 3;
        int i = g * 8 + r;                     // output bin 0..255
        const float*  np = snf + q * 512;
        const float4* Kp = (const float4*)(g_K + (TOFF - 8 * i) + q * 512);

        float4 acc = make_float4(0.f, 0.f, 0.f, 0.f);
        #pragma unroll
        for (int it = 0; it < 4; it++) {       // 4 * 128 = 512 taps per warp
            int m = it * 128 + lane * 4;
            float4 nv = *(const float4*)(np + m);
            float4 kv = __ldg(Kp + (m >> 2));
            acc.x += nv.x * kv.x; acc.y += nv.y * kv.y;
            acc.z += nv.z * kv.z; acc.w += nv.w * kv.w;
        }
        float a = (acc.x + acc.y) + (acc.z + acc.w);
        #pragma unroll
        for (int off = 16; off; off >>= 1)
            a += __shfl_down_sync(0xffffffffu, a, off);
        if (lane == 0) s_part[r][q] = a;
    }
    __syncthreads();

    if (tid < 8) {
        float h  = (s_part[tid][0] + s_part[tid][1]) + (s_part[tid][2] + s_part[tid][3]);
        float pr = h * (1.0f / (float)HW) + 1e-6f;
        s_term[tid] = -pr * logf(pr);
    }
    __syncthreads();

    if (tid == 0) {
        float s = ((s_term[0] + s_term[1]) + (s_term[2] + s_term[3]))
                + ((s_term[4] + s_term[5]) + (s_term[6] + s_term[7]));
        unsigned long long qv = (unsigned long long)((double)s * FXSCALE + 0.5);
        atomicAdd(&g_dacc, qv);
        __threadfence();
        unsigned int old = atomicAdd(&g_done, 1u);
        s_last = (old == 127u);
    }
    __syncthreads();

    // ---- Tail: elected last CTA finalizes + resets state for replay ----
    if (s_last) {
        #pragma unroll
        for (int k = 0; k < (NB * FINE) / NTHR; k++)   // 8192/1024 = 8
            ((unsigned int*)g_nu)[tid + k * NTHR] = 0u;
        if (tid == 0) {
            unsigned long long tot = atomicExch(&g_dacc, 0ULL);
            atomicExch(&g_done, 0u);
            out[0] = (float)(1.0 / ((double)tot * FXINV));
        }
    }
}

extern "C" void kernel_launch(void* const* d_in, const int* in_sizes, int n_in,
                              void* d_out, int out_size) {
    (void)in_sizes; (void)n_in; (void)out_size;
    k_fused<<<GRID, NTHR>>>((const float*)d_in[0], (float*)d_out);
}

// round 13
// speedup vs baseline: 1.3409x; 1.0201x over previous
#include <cuda_runtime.h>
#include <cstdint>

// y (4,1,512,512) fp32; BINS=256, VMIN=0, VMAX=1, SIGMA=30.
// One persistent kernel, 148 CTAs (single wave):
//  Phase 1: per-CTA SHARED 2048-bin fine histogram (smem atomics = measured
//           fastest counting path); export via plain STG to g_shm[cta];
//           signal per-batch counter. NO L2 atomics on the data path.
//  Sync A (batch-local): row-CTAs wait for their batch's 37 hist signals.
//  Merge:   128 row-CTAs each sum a 64-bin slice over 37 sources (coalesced
//           loads) -> float g_n[batch][bin]; signal per-batch merge counter.
//  Sync B (batch-local): wait for 32 merge signals of own batch.
//  Phase 2: correlate g_n with sigmoid-difference table K (8 output bins per
//           CTA); per-CTA entropy partial accumulated in 2^-50 fixed point
//           (exact, order-independent); last-done CTA writes 1/d and resets
//           the counters for graph replay.

#define NB 4
#define HW 262144
#define FINE 2048
#define GRID 148
#define CPB 37                     // histogram CTAs per batch
#define F4B 65536                  // float4 per batch
#define TBL 4096                   // K table alloc (4088 valid)
#define TOFF 2040                  // K index offset: q = idx - TOFF
#define KSTEP (30.0f/2048.0f)
#define NTHR 1024
#define FXSCALE 1125899906842624.0          /* 2^50  */
#define FXINV   8.881784197001252e-16       /* 2^-50 */

__device__ unsigned int       g_shm[GRID][FINE]; // per-CTA hist export (overwritten)
__device__ float              g_n[NB][FINE];     // merged counts (overwritten)
__device__ float              g_K[TBL];          // rebuilt every call (overwritten)
__device__ unsigned long long g_dacc;            // self-reset each call
__device__ unsigned int       g_cnt[NB];         // hist-done per batch; self-reset
__device__ unsigned int       g_cnt2[NB];        // merge-done per batch; self-reset
__device__ unsigned int       g_done;            // row-CTAs done; self-reset

__device__ __forceinline__ float sneg(float t) {       // sigmoid, t <= 0
    float e = expf(t);
    return e / (1.0f + e);
}
__device__ __forceinline__ float sigdiff(float a1, float a2) { // a1 > a2
    if (a2 >= 0.0f) return sneg(-a2) - sneg(-a1);
    if (a1 <= 0.0f) return sneg(a1) - sneg(a2);
    return (1.0f - sneg(-a1)) - sneg(a2);
}

__device__ __forceinline__ int binof(float v) {
    return min((int)(v * 2048.0f), 2047);
}

__global__ void __launch_bounds__(NTHR, 1) k_fused(const float* __restrict__ y,
                                                   float* __restrict__ out) {
    __shared__ unsigned int shh[FINE];       // phase1 hist; phase2 reused as float n
    __shared__ unsigned int s_mrg[8][64];
    __shared__ float s_part[8][4];
    __shared__ float s_term[8];
    __shared__ int   s_last;

    const int tid = threadIdx.x;
    const int cta = blockIdx.x;
    const int b   = cta / CPB;                 // hist batch 0..3
    const int l   = cta - b * CPB;             // local 0..36

    // ---- Issue input loads FIRST (hide DRAM latency behind K/zero/sync) ----
    // split 65536 float4 over 37 CTAs: 9 CTAs get 1772, 28 get 1771
    const int base = b * F4B + l * 1771 + min(l, 9);
    const int len  = 1771 + (l < 9 ? 1 : 0);
    const float4* yp = (const float4*)y;

    float4 v0 = yp[base + tid];
    bool   has2 = (tid + 1024) < len;
    float4 v1;
    if (has2) v1 = yp[base + 1024 + tid];

    // ---- K table: built redundantly by EACH batch (37 CTAs x 111 entries)
    //      so a batch-local wait guarantees K visibility for that batch ----
    if (tid < 111) {
        int idx = l * 111 + tid;
        if (idx < TBL) {
            float v = 0.0f;
            if (idx < TOFF + FINE) {           // 4088 valid
                float q = (float)(idx - TOFF);
                v = sigdiff(KSTEP * (q + 0.5f), KSTEP * (q - 7.5f));
            }
            g_K[idx] = v;
        }
    }

    // ---- Phase 1: per-CTA shared fine histogram ----
    shh[tid] = 0u;
    shh[tid + 1024] = 0u;
    __syncthreads();

    atomicAdd(&shh[binof(v0.x)], 1u);
    atomicAdd(&shh[binof(v0.y)], 1u);
    atomicAdd(&shh[binof(v0.z)], 1u);
    atomicAdd(&shh[binof(v0.w)], 1u);
    if (has2) {
        atomicAdd(&shh[binof(v1.x)], 1u);
        atomicAdd(&shh[binof(v1.y)], 1u);
        atomicAdd(&shh[binof(v1.z)], 1u);
        atomicAdd(&shh[binof(v1.w)], 1u);
    }
    __syncthreads();

    // export hist with plain coalesced stores; signal batch counter
    g_shm[cta][tid]        = shh[tid];
    g_shm[cta][tid + 1024] = shh[tid + 1024];
    __syncthreads();
    if (tid == 0) {
        __threadfence();
        atomicAdd(&g_cnt[b], 1u);
    }

    // ---- hist-only CTAs are done ----
    if (cta >= 128) return;

    const int bb = cta >> 5;                   // phase-2 batch
    const int g  = cta & 31;                   // bin group within batch

    // Sync A: wait for bb's 37 hist exports (covers bb's K writes too)
    if (tid == 0) {
        while (*((volatile unsigned int*)&g_cnt[bb]) < (unsigned)CPB) { }
        __threadfence();
    }
    __syncthreads();

    // ---- Merge: 64-bin slice over 37 sources (pure loads, no atomics) ----
    {
        const int m0 = g * 64;
        if (tid < 512) {
            int sg = tid >> 6;                 // source group 0..7
            int ml = tid & 63;
            unsigned int s = 0;
            #pragma unroll
            for (int k = 0; k < 5; k++) {
                int src = sg + k * 8;
                if (src < CPB)
                    s += g_shm[bb * CPB + src][m0 + ml];
            }
            s_mrg[sg][ml] = s;
        }
        __syncthreads();
        if (tid < 64) {
            unsigned int t = 0;
            #pragma unroll
            for (int i = 0; i < 8; i++) t += s_mrg[i][tid];
            g_n[bb][m0 + tid] = (float)t;
        }
        __syncthreads();
        if (tid == 0) {
            __threadfence();
            atomicAdd(&g_cnt2[bb], 1u);
            // Sync B: wait for all 32 merge slices of batch bb
            while (*((volatile unsigned int*)&g_cnt2[bb]) < 32u) { }
            __threadfence();
        }
        __syncthreads();
    }

    // ---- Phase 2: correlation (8 output bins per CTA) ----
    float* snf = (float*)shh;
    if (tid < FINE / 4)
        ((float4*)snf)[tid] = ((const float4*)g_n[bb])[tid];
    __syncthreads();

    {
        int w = tid >> 5, lane = tid & 31;
        int r = w >> 2, q = w & 3;
        int i = g * 8 + r;                     // output bin 0..255
        const float*  np = snf + q * 512;
        const float4* Kp = (const float4*)(g_K + (TOFF - 8 * i) + q * 512);

        float4 acc = make_float4(0.f, 0.f, 0.f, 0.f);
        #pragma unroll
        for (int it = 0; it < 4; it++) {       // 4 * 128 = 512 taps per warp
            int m = it * 128 + lane * 4;
            float4 nv = *(const float4*)(np + m);
            float4 kv = __ldg(Kp + (m >> 2));
            acc.x += nv.x * kv.x; acc.y += nv.y * kv.y;
            acc.z += nv.z * kv.z; acc.w += nv.w * kv.w;
        }
        float a = (acc.x + acc.y) + (acc.z + acc.w);
        #pragma unroll
        for (int off = 16; off; off >>= 1)
            a += __shfl_down_sync(0xffffffffu, a, off);
        if (lane == 0) s_part[r][q] = a;
    }
    __syncthreads();

    if (tid < 8) {
        float h  = (s_part[tid][0] + s_part[tid][1]) + (s_part[tid][2] + s_part[tid][3]);
        float pr = h * (1.0f / (float)HW) + 1e-6f;
        s_term[tid] = -pr * logf(pr);
    }
    __syncthreads();

    if (tid == 0) {
        float s = ((s_term[0] + s_term[1]) + (s_term[2] + s_term[3]))
                + ((s_term[4] + s_term[5]) + (s_term[6] + s_term[7]));
        unsigned long long qv = (unsigned long long)((double)s * FXSCALE + 0.5);
        atomicAdd(&g_dacc, qv);
        __threadfence();
        unsigned int old = atomicAdd(&g_done, 1u);
        s_last = (old == 127u);
    }
    __syncthreads();

    // ---- Tail: elected last CTA finalizes + resets counters for replay ----
    // Safe: g_done==128 implies every row-CTA passed both spins, and all
    // hist-only CTAs signaled before exiting.
    if (s_last && tid == 0) {
        unsigned long long tot = atomicExch(&g_dacc, 0ULL);
        #pragma unroll
        for (int k = 0; k < NB; k++) {
            atomicExch(&g_cnt[k], 0u);
            atomicExch(&g_cnt2[k], 0u);
        }
        atomicExch(&g_done, 0u);
        out[0] = (float)(1.0 / ((double)tot * FXINV));
    }
}

extern "C" void kernel_launch(void* const* d_in, const int* in_sizes, int n_in,
                              void* d_out, int out_size) {
    (void)in_sizes; (void)n_in; (void)out_size;
    k_fused<<<GRID, NTHR>>>((const float*)d_in[0], (float*)d_out);
}